// round 6
// baseline (speedup 1.0000x reference)
#include <cuda_runtime.h>
#include <cuda_bf16.h>
#include <math.h>
#include <stdint.h>

#define Ntok 1024
#define Dm   2048
#define Fm   5632
#define Em   8
#define Rm   16
#define LSCALE 2.0f
#define K3D  (3*Dm)    // 6144
#define K3F  (3*Fm)    // 16896
#define NBALL (2*Fm + 256)   // 11520
#define FCH  256
#define NCH  (Fm / FCH)      // 22
#define KPER_W2 (K3F / 2)    // 8448

// ---------------- device scratch ----------------
__device__ float g_baseall[(size_t)Ntok * NBALL];
__device__ float g_s    [(size_t)Ntok * 2 * Fm];
__device__ float g_l2p  [(size_t)Ntok * 2 * NCH * 16];
__device__ float g_wpart[(size_t)2 * Ntok * Dm];
__device__ int   g_topi [Ntok * 2];
__device__ float g_topw [Ntok * 2];
__device__ uint32_t g_elist[Em * Ntok];
__device__ int   g_ecnt[Em];
__device__ __align__(256) __nv_bfloat16 g_xcat [(size_t)Ntok  * K3D];
__device__ __align__(256) __nv_bfloat16 g_wallc[(size_t)NBALL * K3D];
__device__ __align__(256) __nv_bfloat16 g_w2c  [(size_t)Dm    * K3F];
__device__ __align__(256) __nv_bfloat16 g_smc  [(size_t)Ntok  * K3F];

// ---------------- PTX helpers ----------------
__device__ __forceinline__ uint32_t s2u(const void* p) {
    uint32_t a;
    asm("{ .reg .u64 t; cvta.to.shared.u64 t, %1; cvt.u32.u64 %0, t; }" : "=r"(a) : "l"(p));
    return a;
}
#define CPA16(d, s) asm volatile("cp.async.cg.shared.global [%0], [%1], 16;" :: "r"(d), "l"(s))
#define LDSM4(R0,R1,R2,R3,addr) asm volatile( \
    "ldmatrix.sync.aligned.m8n8.x4.shared.b16 {%0,%1,%2,%3}, [%4];" \
    : "=r"(R0),"=r"(R1),"=r"(R2),"=r"(R3) : "r"(addr))
#define MMA16816(c, a, b0, b1) asm volatile( \
    "mma.sync.aligned.m16n8k16.row.col.f32.bf16.bf16.f32 " \
    "{%0,%1,%2,%3}, {%4,%5,%6,%7}, {%8,%9}, {%0,%1,%2,%3};" \
    : "+f"((c)[0]),"+f"((c)[1]),"+f"((c)[2]),"+f"((c)[3]) \
    : "r"((a)[0]),"r"((a)[1]),"r"((a)[2]),"r"((a)[3]), "r"(b0),"r"(b1))

// pack 8 fp32 -> (hi uint4, lo uint4) bf16
__device__ __forceinline__ void split8(const float* p, uint4& H, uint4& L) {
    float v[8];
    *(float4*)&v[0] = *(const float4*)p;
    *(float4*)&v[4] = *(const float4*)(p + 4);
    uint32_t h[4], l[4];
    #pragma unroll
    for (int i = 0; i < 4; i++) {
        __nv_bfloat16 h0 = __float2bfloat16(v[2*i]);
        __nv_bfloat16 h1 = __float2bfloat16(v[2*i+1]);
        __nv_bfloat16 l0 = __float2bfloat16(v[2*i]   - __bfloat162float(h0));
        __nv_bfloat16 l1 = __float2bfloat16(v[2*i+1] - __bfloat162float(h1));
        __nv_bfloat162 hp; hp.x = h0; hp.y = h1;
        __nv_bfloat162 lp; lp.x = l0; lp.y = l1;
        h[i] = *(uint32_t*)&hp;
        l[i] = *(uint32_t*)&lp;
    }
    H = make_uint4(h[0], h[1], h[2], h[3]);
    L = make_uint4(l[0], l[1], l[2], l[3]);
}

// ---------------- fp32 -> [hi|hi|lo] (A) or [hi|lo|hi] (B) split, 8 elems/thread ----------------
__global__ void split_kernel(const float* __restrict__ src, __nv_bfloat16* __restrict__ dst,
                             int K, int total8, int bmode) {
    int t = blockIdx.x * 256 + threadIdx.x;
    if (t >= total8) return;
    size_t idx = (size_t)t * 8;
    int row = (int)(idx / K);
    int col = (int)(idx - (size_t)row * K);
    uint4 H, L;
    split8(src + idx, H, L);
    __nv_bfloat16* base = dst + (size_t)row * 3 * K + col;
    *(uint4*)base = H;
    if (bmode) { *(uint4*)(base + K) = L; *(uint4*)(base + 2 * K) = H; }
    else       { *(uint4*)(base + K) = H; *(uint4*)(base + 2 * K) = L; }
}

__global__ void split_a13_kernel(const float* __restrict__ A1, const float* __restrict__ A3,
                                 __nv_bfloat16* __restrict__ dst) {
    int t = blockIdx.x * 256 + threadIdx.x;   // total 256*Dm/8
    size_t idx = (size_t)t * 8;
    int row = (int)(idx / Dm);
    int col = (int)(idx - (size_t)row * Dm);
    int e = row >> 5, rr = row & 31;
    const float* src = (rr < 16) ? (A1 + ((size_t)e * 16 + rr) * Dm)
                                 : (A3 + ((size_t)e * 16 + (rr - 16)) * Dm);
    uint4 H, L;
    split8(src + col, H, L);
    __nv_bfloat16* base = dst + (size_t)row * K3D + col;
    *(uint4*)base = H;
    *(uint4*)(base + Dm) = L;       // B-mode: hi, lo, hi
    *(uint4*)(base + 2 * Dm) = H;
}

// ======== HMMA GEMM: 128x128 tile, warp 64x32, BK=64, 3-stage, 1 sync/iter ========
#define NSTG 3
#define RP   144
#define STG_BYTES (256 * RP)          // 36864
#define GEMM_SMEM (NSTG * STG_BYTES)  // 110592
#define B_OFF (128 * RP)              // 18432

__global__ void __launch_bounds__(256, 2)
gemm_mma(const __nv_bfloat16* __restrict__ Ag, const __nv_bfloat16* __restrict__ Bg,
         float* __restrict__ Cg, int Nn, int Kfull, int Kper) {
    extern __shared__ char smraw[];
    const uint32_t sb = s2u(smraw);
    const int tid = threadIdx.x;
    const int lane = tid & 31, wid = tid >> 5;
    const int wm = wid & 1, wn = wid >> 1;
    const int bm = blockIdx.x * 128, bn = blockIdx.y * 128;
    const int koff = blockIdx.z * Kper;
    float* Cz = Cg + (size_t)blockIdx.z * Ntok * Nn;
    const int nk = Kper >> 6;

    // global->smem: 2 threads per row, each 64B (4 x cp.async.16)
    const int r = tid >> 1, part = tid & 1;
    const __nv_bfloat16* gA = Ag + (size_t)(bm + r) * Kfull + koff + part * 32;
    const __nv_bfloat16* gB = Bg + (size_t)(bn + r) * Kfull + koff + part * 32;
    const uint32_t dA = sb + r * RP + part * 64;
    const uint32_t dB = sb + B_OFF + r * RP + part * 64;

    // ldmatrix lane addressing
    const uint32_t lrow = (uint32_t)(lane & 15);
    const uint32_t hib  = (uint32_t)(lane >> 4) * 16;
    const uint32_t aLd = sb + (wm * 64 + lrow) * RP + hib;
    const uint32_t bLd = sb + B_OFF + (wn * 32 + lrow) * RP + hib;

    float acc[4][4][4];
    #pragma unroll
    for (int i = 0; i < 4; i++)
        #pragma unroll
        for (int j = 0; j < 4; j++)
            #pragma unroll
            for (int q = 0; q < 4; q++) acc[i][j][q] = 0.f;

    // prologue: stages 0,1
    #pragma unroll
    for (int s = 0; s < 2; s++) {
        uint32_t so = (uint32_t)s * STG_BYTES;
        const __nv_bfloat16* a = gA + s * 64;
        const __nv_bfloat16* b = gB + s * 64;
        #pragma unroll
        for (int i = 0; i < 4; i++) { CPA16(dA + so + i * 16, a + i * 8); }
        #pragma unroll
        for (int i = 0; i < 4; i++) { CPA16(dB + so + i * 16, b + i * 8); }
        asm volatile("cp.async.commit_group;" ::: "memory");
    }

    int sc = 0, sp = 2;   // compute stage, prefetch stage
    for (int kt = 0; kt < nk; kt++) {
        asm volatile("cp.async.wait_group 1;" ::: "memory");
        __syncthreads();

        const uint32_t so = sb ? (uint32_t)sc * STG_BYTES : 0u;  // keep sc usage
        const uint32_t soc = (uint32_t)sc * STG_BYTES;
        #pragma unroll
        for (int ks = 0; ks < 4; ks++) {
            uint32_t Ar[4][4], Br[2][4];
            #pragma unroll
            for (int mt = 0; mt < 4; mt++)
                LDSM4(Ar[mt][0], Ar[mt][1], Ar[mt][2], Ar[mt][3],
                      aLd + soc + mt * (16 * RP) + ks * 32);
            #pragma unroll
            for (int p = 0; p < 2; p++)
                LDSM4(Br[p][0], Br[p][1], Br[p][2], Br[p][3],
                      bLd + soc + p * (16 * RP) + ks * 32);
            #pragma unroll
            for (int mt = 0; mt < 4; mt++)
                #pragma unroll
                for (int nt = 0; nt < 4; nt++) {
                    uint32_t b0 = Br[nt >> 1][nt & 1];
                    uint32_t b1 = Br[nt >> 1][2 + (nt & 1)];
                    MMA16816(acc[mt][nt], Ar[mt], b0, b1);
                }
        }
        (void)so;

        int ls = kt + 2;
        if (ls < nk) {
            uint32_t so2 = (uint32_t)sp * STG_BYTES;
            const __nv_bfloat16* a = gA + (size_t)ls * 64;
            const __nv_bfloat16* b = gB + (size_t)ls * 64;
            #pragma unroll
            for (int i = 0; i < 4; i++) { CPA16(dA + so2 + i * 16, a + i * 8); }
            #pragma unroll
            for (int i = 0; i < 4; i++) { CPA16(dB + so2 + i * 16, b + i * 8); }
        }
        asm volatile("cp.async.commit_group;" ::: "memory");

        sc = (sc == 2) ? 0 : sc + 1;
        sp = (sp == 2) ? 0 : sp + 1;
    }

    const int g = lane >> 2, t4 = lane & 3;
    #pragma unroll
    for (int mt = 0; mt < 4; mt++) {
        int row = bm + wm * 64 + mt * 16 + g;
        #pragma unroll
        for (int nt = 0; nt < 4; nt++) {
            int col = bn + wn * 32 + nt * 8 + 2 * t4;
            *(float2*)(Cz + (size_t)row * Nn + col)       = make_float2(acc[mt][nt][0], acc[mt][nt][1]);
            *(float2*)(Cz + (size_t)(row + 8) * Nn + col) = make_float2(acc[mt][nt][2], acc[mt][nt][3]);
        }
    }
}

// ---------------- router ----------------
__global__ void gate_kernel(const float* __restrict__ x,
                            const float* __restrict__ gw,
                            float* __restrict__ logits_out) {
    int n = blockIdx.x;
    int tid = threadIdx.x;
    __shared__ float sx[Dm];
    for (int i = tid; i < Dm; i += 256) sx[i] = x[(size_t)n * Dm + i];
    __syncthreads();
    int w = tid >> 5, lane = tid & 31;
    const float* g = gw + (size_t)w * Dm;
    float sum = 0.f;
    for (int d = lane; d < Dm; d += 32) sum += sx[d] * g[d];
    #pragma unroll
    for (int o = 16; o; o >>= 1) sum += __shfl_down_sync(0xffffffffu, sum, o);
    __shared__ float slog[Em];
    if (lane == 0) slog[w] = sum;
    __syncthreads();
    if (tid == 0) {
        float mx = slog[0];
        #pragma unroll
        for (int e = 1; e < Em; e++) mx = fmaxf(mx, slog[e]);
        float p[Em], Z = 0.f;
        #pragma unroll
        for (int e = 0; e < Em; e++) { p[e] = expf(slog[e] - mx); Z += p[e]; }
        #pragma unroll
        for (int e = 0; e < Em; e++) p[e] /= Z;
        int i0 = 0;
        #pragma unroll
        for (int e = 1; e < Em; e++) if (p[e] > p[i0]) i0 = e;
        int i1 = (i0 == 0) ? 1 : 0;
        #pragma unroll
        for (int e = 0; e < Em; e++) { if (e == i0 || e == i1) continue; if (p[e] > p[i1]) i1 = e; }
        float w0 = p[i0], w1 = p[i1], s = w0 + w1;
        g_topi[n * 2 + 0] = i0; g_topi[n * 2 + 1] = i1;
        g_topw[n * 2 + 0] = w0 / s; g_topw[n * 2 + 1] = w1 / s;
        #pragma unroll
        for (int e = 0; e < Em; e++) logits_out[(size_t)n * Em + e] = slog[e];
    }
}

// ---------------- deterministic per-expert token lists ----------------
__global__ void build_list_kernel() {
    int e = blockIdx.x;
    int tid = threadIdx.x;
    __shared__ int wcnt[8];
    __shared__ int base;
    if (tid == 0) base = 0;
    __syncthreads();
    for (int t0 = 0; t0 < Ntok; t0 += 256) {
        int n = t0 + tid;
        int k = -1;
        if (g_topi[2 * n] == e) k = 0;
        else if (g_topi[2 * n + 1] == e) k = 1;
        unsigned b = __ballot_sync(0xffffffffu, k >= 0);
        int lane = tid & 31, w = tid >> 5;
        if (lane == 0) wcnt[w] = __popc(b);
        __syncthreads();
        int off = base;
        for (int ww = 0; ww < w; ww++) off += wcnt[ww];
        off += __popc(b & ((1u << lane) - 1));
        if (k >= 0) g_elist[e * Ntok + off] = (uint32_t)n | ((uint32_t)k << 16);
        __syncthreads();
        if (tid == 0) {
            int tot = 0;
            for (int ww = 0; ww < 8; ww++) tot += wcnt[ww];
            base += tot;
        }
        __syncthreads();
    }
    if (tid == 0) g_ecnt[e] = base;
}

// ---------------- expert-major SwiGLU, warp-per-token ----------------
#define EFFN_SMEM (48 * FCH * 4)
__global__ void __launch_bounds__(256)
expert_ffn(const float* __restrict__ B1, const float* __restrict__ B3,
           const float* __restrict__ A2) {
    int e = blockIdx.x, ch = blockIdx.y;
    int f0 = ch * FCH;
    extern __shared__ float sm[];
    float* B1s = sm;
    float* B3s = sm + 16 * FCH;
    float* A2s = sm + 32 * FCH;
    int tid = threadIdx.x, lane = tid & 31, wid = tid >> 5;

    {
        const float4* p1 = (const float4*)(B1 + ((size_t)e * Fm + f0 + tid) * 16);
        const float4* p3 = (const float4*)(B3 + ((size_t)e * Fm + f0 + tid) * 16);
        #pragma unroll
        for (int q = 0; q < 4; q++) {
            float4 v1 = p1[q], v3 = p3[q];
            B1s[(4*q+0)*FCH + tid] = v1.x; B1s[(4*q+1)*FCH + tid] = v1.y;
            B1s[(4*q+2)*FCH + tid] = v1.z; B1s[(4*q+3)*FCH + tid] = v1.w;
            B3s[(4*q+0)*FCH + tid] = v3.x; B3s[(4*q+1)*FCH + tid] = v3.y;
            B3s[(4*q+2)*FCH + tid] = v3.z; B3s[(4*q+3)*FCH + tid] = v3.w;
        }
        #pragma unroll
        for (int rr = 0; rr < 16; rr++)
            A2s[rr * FCH + tid] = A2[((size_t)e * 16 + rr) * Fm + f0 + tid];
    }
    __syncthreads();

    int cnt = g_ecnt[e];
    for (int i = wid; i < cnt; i += 8) {
        uint32_t pk = g_elist[e * Ntok + i];
        int n = pk & 0xFFFF, k = (int)(pk >> 16);
        float l13 = g_baseall[(size_t)n * NBALL + 2 * Fm + e * 32 + lane];
        float l1r[16], l3r[16];
        #pragma unroll
        for (int rr = 0; rr < 16; rr++) {
            l1r[rr] = __shfl_sync(0xffffffffu, l13, rr);
            l3r[rr] = __shfl_sync(0xffffffffu, l13, 16 + rr);
        }
        float l2a[16];
        #pragma unroll
        for (int rr = 0; rr < 16; rr++) l2a[rr] = 0.f;

        const float* brow = g_baseall + (size_t)n * NBALL;
        float* srow = g_s + ((size_t)n * 2 + k) * Fm;
        #pragma unroll
        for (int fi = 0; fi < 8; fi++) {
            int fl = fi * 32 + lane;
            float b1v = brow[f0 + fl];
            float b3v = brow[Fm + f0 + fl];
            float h1 = 0.f, h3 = 0.f;
            #pragma unroll
            for (int rr = 0; rr < 16; rr++) {
                h1 = fmaf(l1r[rr], B1s[rr * FCH + fl], h1);
                h3 = fmaf(l3r[rr], B3s[rr * FCH + fl], h3);
            }
            h1 = fmaf(LSCALE, h1, b1v);
            h3 = fmaf(LSCALE, h3, b3v);
            float sig = 1.f / (1.f + expf(-h1));
            float s = h1 * sig * h3;
            srow[f0 + fl] = s;
            #pragma unroll
            for (int rr = 0; rr < 16; rr++)
                l2a[rr] = fmaf(s, A2s[rr * FCH + fl], l2a[rr]);
        }
        #pragma unroll
        for (int rr = 0; rr < 16; rr++) {
            float v = l2a[rr];
            #pragma unroll
            for (int o = 16; o; o >>= 1) v += __shfl_down_sync(0xffffffffu, v, o);
            if (lane == 0)
                g_l2p[(((size_t)n * 2 + k) * NCH + ch) * 16 + rr] = v;
        }
    }
}

// ---------------- mix + bf16 split of smix (A-mode), 8 elems/thread ----------------
__global__ void mix_split_kernel() {
    int t = blockIdx.x * 256 + threadIdx.x;
    size_t idx = (size_t)t * 8;
    int n = (int)(idx / Fm);
    int f = (int)(idx - (size_t)n * Fm);
    float w0 = g_topw[2 * n], w1 = g_topw[2 * n + 1];
    const float* s0p = g_s + ((size_t)n * 2) * Fm + f;
    const float* s1p = g_s + ((size_t)n * 2 + 1) * Fm + f;
    float m[8];
    #pragma unroll
    for (int q = 0; q < 2; q++) {
        float4 a = *(const float4*)(s0p + 4 * q);
        float4 b = *(const float4*)(s1p + 4 * q);
        m[4*q+0] = w0 * a.x + w1 * b.x;
        m[4*q+1] = w0 * a.y + w1 * b.y;
        m[4*q+2] = w0 * a.z + w1 * b.z;
        m[4*q+3] = w0 * a.w + w1 * b.w;
    }
    uint32_t h[4], l[4];
    #pragma unroll
    for (int i = 0; i < 4; i++) {
        __nv_bfloat16 h0 = __float2bfloat16(m[2*i]);
        __nv_bfloat16 h1 = __float2bfloat16(m[2*i+1]);
        __nv_bfloat16 l0 = __float2bfloat16(m[2*i]   - __bfloat162float(h0));
        __nv_bfloat16 l1 = __float2bfloat16(m[2*i+1] - __bfloat162float(h1));
        __nv_bfloat162 hp; hp.x = h0; hp.y = h1;
        __nv_bfloat162 lp; lp.x = l0; lp.y = l1;
        h[i] = *(uint32_t*)&hp;
        l[i] = *(uint32_t*)&lp;
    }
    uint4 H = make_uint4(h[0], h[1], h[2], h[3]);
    uint4 L = make_uint4(l[0], l[1], l[2], l[3]);
    __nv_bfloat16* base = g_smc + (size_t)n * K3F + f;
    *(uint4*)base = H;
    *(uint4*)(base + Fm) = H;       // A-mode: hi, hi, lo
    *(uint4*)(base + 2 * Fm) = L;
}

// ---------------- output: split-K merge + LoRA ----------------
__global__ void lora_out_kernel(const float* __restrict__ B2, float* __restrict__ out) {
    int n = blockIdx.y;
    int d = blockIdx.x * 256 + threadIdx.x;
    __shared__ float sl2[32];
    __shared__ int se[2];
    if (threadIdx.x < 32) {
        int k = threadIdx.x >> 4, rr = threadIdx.x & 15;
        float v = 0.f;
        #pragma unroll
        for (int ch = 0; ch < NCH; ch++)
            v += g_l2p[(((size_t)n * 2 + k) * NCH + ch) * 16 + rr];
        sl2[threadIdx.x] = v * g_topw[n * 2 + k] * LSCALE;
    }
    if (threadIdx.x < 2) se[threadIdx.x] = g_topi[n * 2 + threadIdx.x];
    __syncthreads();
    float acc = g_wpart[(size_t)n * Dm + d] + g_wpart[(size_t)Ntok * Dm + (size_t)n * Dm + d];
    #pragma unroll
    for (int k = 0; k < 2; k++) {
        int e = se[k];
        const float4* bp = (const float4*)(B2 + ((size_t)e * Dm + d) * Rm);
        #pragma unroll
        for (int q = 0; q < 4; q++) {
            float4 v = bp[q];
            acc += sl2[k*16+4*q+0]*v.x + sl2[k*16+4*q+1]*v.y + sl2[k*16+4*q+2]*v.z + sl2[k*16+4*q+3]*v.w;
        }
    }
    out[(size_t)n * Dm + d] = acc;
}

// --------------------------------- launch --------------------------------
extern "C" void kernel_launch(void* const* d_in, const int* in_sizes, int n_in,
                              void* d_out, int out_size) {
    const float* x      = (const float*)d_in[0];
    const float* gate_w = (const float*)d_in[1];
    const float* W1     = (const float*)d_in[2];
    const float* W3     = (const float*)d_in[3];
    const float* W2     = (const float*)d_in[4];
    const float* A1     = (const float*)d_in[5];
    const float* B1     = (const float*)d_in[6];
    const float* A3     = (const float*)d_in[7];
    const float* B3     = (const float*)d_in[8];
    const float* A2     = (const float*)d_in[9];
    const float* B2     = (const float*)d_in[10];

    float* out    = (float*)d_out;
    float* logits = (float*)d_out + (size_t)Ntok * Dm;

    float *baseall, *wpart;
    __nv_bfloat16 *xcat, *wallc, *w2c, *smc;
    cudaGetSymbolAddress((void**)&baseall, g_baseall);
    cudaGetSymbolAddress((void**)&wpart, g_wpart);
    cudaGetSymbolAddress((void**)&xcat,  g_xcat);
    cudaGetSymbolAddress((void**)&wallc, g_wallc);
    cudaGetSymbolAddress((void**)&w2c,   g_w2c);
    cudaGetSymbolAddress((void**)&smc,   g_smc);

    cudaFuncSetAttribute(gemm_mma, cudaFuncAttributeMaxDynamicSharedMemorySize, GEMM_SMEM);
    cudaFuncSetAttribute(expert_ffn, cudaFuncAttributeMaxDynamicSharedMemorySize, EFFN_SMEM);

    // splits (8 elems/thread)
    split_kernel<<<Ntok * Dm / 8 / 256, 256>>>(x, xcat, Dm, Ntok * Dm / 8, 0);
    split_kernel<<<Fm * Dm / 8 / 256, 256>>>(W1, wallc, Dm, Fm * Dm / 8, 1);
    split_kernel<<<Fm * Dm / 8 / 256, 256>>>(W3, wallc + (size_t)Fm * K3D, Dm, Fm * Dm / 8, 1);
    split_a13_kernel<<<256 * Dm / 8 / 256, 256>>>(A1, A3, wallc + (size_t)2 * Fm * K3D);
    split_kernel<<<Dm * Fm / 8 / 256, 256>>>(W2, w2c, Fm, Dm * Fm / 8, 1);

    // router + expert lists
    gate_kernel<<<Ntok, 256>>>(x, gate_w, logits);
    build_list_kernel<<<Em, 256>>>();

    // fused base GEMM: [x@W1 | x@W3 | x@A13]
    {
        dim3 grid(Ntok / 128, NBALL / 128, 1);   // 8 x 90
        gemm_mma<<<grid, 256, GEMM_SMEM>>>(xcat, wallc, baseall, NBALL, K3D, K3D);
    }
    // expert-major SwiGLU + l2 partials
    {
        dim3 grid(Em, NCH);
        expert_ffn<<<grid, 256, EFFN_SMEM>>>(B1, B3, A2);
    }
    // mix + split
    mix_split_kernel<<<Ntok * Fm / 8 / 256, 256>>>();
    // down-projection GEMM, split-K=2
    {
        dim3 grid(Ntok / 128, Dm / 128, 2);      // 8 x 16 x 2
        gemm_mma<<<grid, 256, GEMM_SMEM>>>(smc, w2c, wpart, Dm, K3F, KPER_W2);
    }
    // merge partials + output LoRA
    {
        dim3 grid(Dm / 256, Ntok);
        lora_out_kernel<<<grid, 256>>>(B2, out);
    }
}

// round 7
// speedup vs baseline: 1.1490x; 1.1490x over previous
#include <cuda_runtime.h>
#include <cuda_bf16.h>
#include <math.h>
#include <stdint.h>

#define Ntok 1024
#define Dm   2048
#define Fm   5632
#define Em   8
#define Rm   16
#define LSCALE 2.0f
#define K3D  (3*Dm)    // 6144
#define K3F  (3*Fm)    // 16896
#define NBALL (2*Fm + 256)   // 11520
#define FCH  256
#define NCH  (Fm / FCH)      // 22
#define ZW2  4
#define KPER_W2 (K3F / ZW2)  // 4224
#define NPERSIST 592

// ---------------- device scratch ----------------
__device__ float g_baseall[(size_t)Ntok * NBALL];
__device__ float g_s    [(size_t)Ntok * 2 * Fm];
__device__ float g_l2p  [(size_t)Ntok * 2 * NCH * 16];
__device__ float g_wpart[(size_t)ZW2 * Ntok * Dm];
__device__ int   g_topi [Ntok * 2];
__device__ float g_topw [Ntok * 2];
__device__ uint32_t g_elist[Em * Ntok];
__device__ int   g_ecnt[Em];
__device__ __align__(256) __nv_bfloat16 g_xcat [(size_t)Ntok  * K3D];
__device__ __align__(256) __nv_bfloat16 g_wallc[(size_t)NBALL * K3D];
__device__ __align__(256) __nv_bfloat16 g_w2c  [(size_t)Dm    * K3F];
__device__ __align__(256) __nv_bfloat16 g_smc  [(size_t)Ntok  * K3F];

// ---------------- PTX helpers ----------------
__device__ __forceinline__ uint32_t s2u(const void* p) {
    uint32_t a;
    asm("{ .reg .u64 t; cvta.to.shared.u64 t, %1; cvt.u32.u64 %0, t; }" : "=r"(a) : "l"(p));
    return a;
}
#define CPA16(d, s) asm volatile("cp.async.cg.shared.global [%0], [%1], 16;" :: "r"(d), "l"(s))
#define LDSM4(R0,R1,R2,R3,addr) asm volatile( \
    "ldmatrix.sync.aligned.m8n8.x4.shared.b16 {%0,%1,%2,%3}, [%4];" \
    : "=r"(R0),"=r"(R1),"=r"(R2),"=r"(R3) : "r"(addr))
#define MMA16816(c, a, b0, b1) asm volatile( \
    "mma.sync.aligned.m16n8k16.row.col.f32.bf16.bf16.f32 " \
    "{%0,%1,%2,%3}, {%4,%5,%6,%7}, {%8,%9}, {%0,%1,%2,%3};" \
    : "+f"((c)[0]),"+f"((c)[1]),"+f"((c)[2]),"+f"((c)[3]) \
    : "r"((a)[0]),"r"((a)[1]),"r"((a)[2]),"r"((a)[3]), "r"(b0),"r"(b1))

// pack 8 fp32 -> (hi uint4, lo uint4) bf16
__device__ __forceinline__ void split8(const float* p, uint4& H, uint4& L) {
    float v[8];
    *(float4*)&v[0] = *(const float4*)p;
    *(float4*)&v[4] = *(const float4*)(p + 4);
    uint32_t h[4], l[4];
    #pragma unroll
    for (int i = 0; i < 4; i++) {
        __nv_bfloat16 h0 = __float2bfloat16(v[2*i]);
        __nv_bfloat16 h1 = __float2bfloat16(v[2*i+1]);
        __nv_bfloat16 l0 = __float2bfloat16(v[2*i]   - __bfloat162float(h0));
        __nv_bfloat16 l1 = __float2bfloat16(v[2*i+1] - __bfloat162float(h1));
        __nv_bfloat162 hp; hp.x = h0; hp.y = h1;
        __nv_bfloat162 lp; lp.x = l0; lp.y = l1;
        h[i] = *(uint32_t*)&hp;
        l[i] = *(uint32_t*)&lp;
    }
    H = make_uint4(h[0], h[1], h[2], h[3]);
    L = make_uint4(l[0], l[1], l[2], l[3]);
}

// ---------------- fp32 -> [hi|hi|lo] (A) or [hi|lo|hi] (B) split ----------------
__global__ void split_kernel(const float* __restrict__ src, __nv_bfloat16* __restrict__ dst,
                             int K, int total8, int bmode) {
    int t = blockIdx.x * 256 + threadIdx.x;
    if (t >= total8) return;
    size_t idx = (size_t)t * 8;
    int row = (int)(idx / K);
    int col = (int)(idx - (size_t)row * K);
    uint4 H, L;
    split8(src + idx, H, L);
    __nv_bfloat16* base = dst + (size_t)row * 3 * K + col;
    *(uint4*)base = H;
    if (bmode) { *(uint4*)(base + K) = L; *(uint4*)(base + 2 * K) = H; }
    else       { *(uint4*)(base + K) = H; *(uint4*)(base + 2 * K) = L; }
}

__global__ void split_a13_kernel(const float* __restrict__ A1, const float* __restrict__ A3,
                                 __nv_bfloat16* __restrict__ dst) {
    int t = blockIdx.x * 256 + threadIdx.x;
    size_t idx = (size_t)t * 8;
    int row = (int)(idx / Dm);
    int col = (int)(idx - (size_t)row * Dm);
    int e = row >> 5, rr = row & 31;
    const float* src = (rr < 16) ? (A1 + ((size_t)e * 16 + rr) * Dm)
                                 : (A3 + ((size_t)e * 16 + (rr - 16)) * Dm);
    uint4 H, L;
    split8(src + col, H, L);
    __nv_bfloat16* base = dst + (size_t)row * K3D + col;
    *(uint4*)base = H;
    *(uint4*)(base + Dm) = L;
    *(uint4*)(base + 2 * Dm) = H;
}

// ======== persistent HMMA GEMM: 128x128 tile, warp 64x32, BK=32, 4-stage, 1 bar/iter ========
#define NSTAGE      4
#define STAGE_BYTES 10240
#define BBUF_OFF    (NSTAGE * STAGE_BYTES)
#define GEMM_SMEM   (2 * BBUF_OFF)

__global__ void __launch_bounds__(256, 2)
gemm_mma(const __nv_bfloat16* __restrict__ Ag, const __nv_bfloat16* __restrict__ Bg,
         float* __restrict__ Cg, int Nn, int Kfull, int Kper,
         int gridM, int gridN, int ntiles) {
    extern __shared__ char smraw[];
    const uint32_t sb = s2u(smraw);
    const int tid = threadIdx.x;
    const int lane = tid & 31, wid = tid >> 5;
    const int wm = wid & 1, wn = wid >> 1;
    const int nk = Kper >> 5;

    const int r = tid >> 1, half = tid & 1;
    const uint32_t dA = sb + r * 80 + half * 32;
    const uint32_t dB = sb + BBUF_OFF + r * 80 + half * 32;

    const uint32_t lrow = (uint32_t)(lane & 15);
    const uint32_t lcolb = (uint32_t)(lane >> 4) * 16;
    const uint32_t aLd = sb + (wm * 64 + lrow) * 80 + lcolb;
    const uint32_t bLd = sb + BBUF_OFF + (wn * 32 + lrow) * 80 + lcolb;

    for (int t = blockIdx.x; t < ntiles; t += gridDim.x) {
        int tm = t % gridM;
        int rem = t / gridM;
        int tn = rem % gridN;
        int z  = rem / gridN;
        const int bm = tm * 128, bn = tn * 128;
        const int koff = z * Kper;
        float* Cz = Cg + (size_t)z * (size_t)(gridM * 128) * Nn;

        const __nv_bfloat16* gA = Ag + (size_t)(bm + r) * Kfull + koff + half * 16;
        const __nv_bfloat16* gB = Bg + (size_t)(bn + r) * Kfull + koff + half * 16;

        float acc[4][4][4];
        #pragma unroll
        for (int i = 0; i < 4; i++)
            #pragma unroll
            for (int j = 0; j < 4; j++)
                #pragma unroll
                for (int q = 0; q < 4; q++) acc[i][j][q] = 0.f;

        #pragma unroll
        for (int s = 0; s < NSTAGE - 1; s++) {
            const __nv_bfloat16* a = gA + s * 32;
            const __nv_bfloat16* b = gB + s * 32;
            uint32_t so = (uint32_t)s * STAGE_BYTES;
            CPA16(dA + so, a); CPA16(dA + so + 16, a + 8);
            CPA16(dB + so, b); CPA16(dB + so + 16, b + 8);
            asm volatile("cp.async.commit_group;" ::: "memory");
        }

        for (int kt = 0; kt < nk; kt++) {
            asm volatile("cp.async.wait_group 2;" ::: "memory");
            __syncthreads();

            const uint32_t so = (uint32_t)(kt & (NSTAGE - 1)) * STAGE_BYTES;
            #pragma unroll
            for (int ks = 0; ks < 2; ks++) {
                uint32_t Ar[4][4], Br[2][4];
                #pragma unroll
                for (int mt = 0; mt < 4; mt++)
                    LDSM4(Ar[mt][0], Ar[mt][1], Ar[mt][2], Ar[mt][3],
                          aLd + so + mt * 1280 + ks * 32);
                #pragma unroll
                for (int p = 0; p < 2; p++)
                    LDSM4(Br[p][0], Br[p][1], Br[p][2], Br[p][3],
                          bLd + so + p * 1280 + ks * 32);
                #pragma unroll
                for (int mt = 0; mt < 4; mt++)
                    #pragma unroll
                    for (int nt = 0; nt < 4; nt++) {
                        uint32_t b0 = Br[nt >> 1][nt & 1];
                        uint32_t b1 = Br[nt >> 1][2 + (nt & 1)];
                        MMA16816(acc[mt][nt], Ar[mt], b0, b1);
                    }
            }

            int ls = kt + NSTAGE - 1;
            if (ls < nk) {
                uint32_t so2 = (uint32_t)(ls & (NSTAGE - 1)) * STAGE_BYTES;
                const __nv_bfloat16* a = gA + (size_t)ls * 32;
                const __nv_bfloat16* b = gB + (size_t)ls * 32;
                CPA16(dA + so2, a); CPA16(dA + so2 + 16, a + 8);
                CPA16(dB + so2, b); CPA16(dB + so2 + 16, b + 8);
            }
            asm volatile("cp.async.commit_group;" ::: "memory");
        }

        const int g = lane >> 2, t4 = lane & 3;
        #pragma unroll
        for (int mt = 0; mt < 4; mt++) {
            int row = bm + wm * 64 + mt * 16 + g;
            #pragma unroll
            for (int nt = 0; nt < 4; nt++) {
                int col = bn + wn * 32 + nt * 8 + 2 * t4;
                *(float2*)(Cz + (size_t)row * Nn + col)       = make_float2(acc[mt][nt][0], acc[mt][nt][1]);
                *(float2*)(Cz + (size_t)(row + 8) * Nn + col) = make_float2(acc[mt][nt][2], acc[mt][nt][3]);
            }
        }
        asm volatile("cp.async.wait_group 0;" ::: "memory");
        __syncthreads();
    }
}

// ---------------- router ----------------
__global__ void gate_kernel(const float* __restrict__ x,
                            const float* __restrict__ gw,
                            float* __restrict__ logits_out) {
    int n = blockIdx.x;
    int tid = threadIdx.x;
    __shared__ float sx[Dm];
    for (int i = tid; i < Dm; i += 256) sx[i] = x[(size_t)n * Dm + i];
    __syncthreads();
    int w = tid >> 5, lane = tid & 31;
    const float* g = gw + (size_t)w * Dm;
    float sum = 0.f;
    for (int d = lane; d < Dm; d += 32) sum += sx[d] * g[d];
    #pragma unroll
    for (int o = 16; o; o >>= 1) sum += __shfl_down_sync(0xffffffffu, sum, o);
    __shared__ float slog[Em];
    if (lane == 0) slog[w] = sum;
    __syncthreads();
    if (tid == 0) {
        float mx = slog[0];
        #pragma unroll
        for (int e = 1; e < Em; e++) mx = fmaxf(mx, slog[e]);
        float p[Em], Z = 0.f;
        #pragma unroll
        for (int e = 0; e < Em; e++) { p[e] = expf(slog[e] - mx); Z += p[e]; }
        #pragma unroll
        for (int e = 0; e < Em; e++) p[e] /= Z;
        int i0 = 0;
        #pragma unroll
        for (int e = 1; e < Em; e++) if (p[e] > p[i0]) i0 = e;
        int i1 = (i0 == 0) ? 1 : 0;
        #pragma unroll
        for (int e = 0; e < Em; e++) { if (e == i0 || e == i1) continue; if (p[e] > p[i1]) i1 = e; }
        float w0 = p[i0], w1 = p[i1], s = w0 + w1;
        g_topi[n * 2 + 0] = i0; g_topi[n * 2 + 1] = i1;
        g_topw[n * 2 + 0] = w0 / s; g_topw[n * 2 + 1] = w1 / s;
        #pragma unroll
        for (int e = 0; e < Em; e++) logits_out[(size_t)n * Em + e] = slog[e];
    }
}

// ---------------- deterministic per-expert token lists ----------------
__global__ void build_list_kernel() {
    int e = blockIdx.x;
    int tid = threadIdx.x;
    __shared__ int wcnt[8];
    __shared__ int base;
    if (tid == 0) base = 0;
    __syncthreads();
    for (int t0 = 0; t0 < Ntok; t0 += 256) {
        int n = t0 + tid;
        int k = -1;
        if (g_topi[2 * n] == e) k = 0;
        else if (g_topi[2 * n + 1] == e) k = 1;
        unsigned b = __ballot_sync(0xffffffffu, k >= 0);
        int lane = tid & 31, w = tid >> 5;
        if (lane == 0) wcnt[w] = __popc(b);
        __syncthreads();
        int off = base;
        for (int ww = 0; ww < w; ww++) off += wcnt[ww];
        off += __popc(b & ((1u << lane) - 1));
        if (k >= 0) g_elist[e * Ntok + off] = (uint32_t)n | ((uint32_t)k << 16);
        __syncthreads();
        if (tid == 0) {
            int tot = 0;
            for (int ww = 0; ww < 8; ww++) tot += wcnt[ww];
            base += tot;
        }
        __syncthreads();
    }
    if (tid == 0) g_ecnt[e] = base;
}

// ---------------- expert-major SwiGLU, warp-per-token ----------------
#define EFFN_SMEM (48 * FCH * 4)
__global__ void __launch_bounds__(256)
expert_ffn(const float* __restrict__ B1, const float* __restrict__ B3,
           const float* __restrict__ A2) {
    int e = blockIdx.x, ch = blockIdx.y;
    int f0 = ch * FCH;
    extern __shared__ float sm[];
    float* B1s = sm;
    float* B3s = sm + 16 * FCH;
    float* A2s = sm + 32 * FCH;
    int tid = threadIdx.x, lane = tid & 31, wid = tid >> 5;

    {
        const float4* p1 = (const float4*)(B1 + ((size_t)e * Fm + f0 + tid) * 16);
        const float4* p3 = (const float4*)(B3 + ((size_t)e * Fm + f0 + tid) * 16);
        #pragma unroll
        for (int q = 0; q < 4; q++) {
            float4 v1 = p1[q], v3 = p3[q];
            B1s[(4*q+0)*FCH + tid] = v1.x; B1s[(4*q+1)*FCH + tid] = v1.y;
            B1s[(4*q+2)*FCH + tid] = v1.z; B1s[(4*q+3)*FCH + tid] = v1.w;
            B3s[(4*q+0)*FCH + tid] = v3.x; B3s[(4*q+1)*FCH + tid] = v3.y;
            B3s[(4*q+2)*FCH + tid] = v3.z; B3s[(4*q+3)*FCH + tid] = v3.w;
        }
        #pragma unroll
        for (int rr = 0; rr < 16; rr++)
            A2s[rr * FCH + tid] = A2[((size_t)e * 16 + rr) * Fm + f0 + tid];
    }
    __syncthreads();

    int cnt = g_ecnt[e];
    for (int i = wid; i < cnt; i += 8) {
        uint32_t pk = g_elist[e * Ntok + i];
        int n = pk & 0xFFFF, k = (int)(pk >> 16);
        float l13 = g_baseall[(size_t)n * NBALL + 2 * Fm + e * 32 + lane];
        float l1r[16], l3r[16];
        #pragma unroll
        for (int rr = 0; rr < 16; rr++) {
            l1r[rr] = __shfl_sync(0xffffffffu, l13, rr);
            l3r[rr] = __shfl_sync(0xffffffffu, l13, 16 + rr);
        }
        float l2a[16];
        #pragma unroll
        for (int rr = 0; rr < 16; rr++) l2a[rr] = 0.f;

        const float* brow = g_baseall + (size_t)n * NBALL;
        float* srow = g_s + ((size_t)n * 2 + k) * Fm;
        #pragma unroll
        for (int fi = 0; fi < 8; fi++) {
            int fl = fi * 32 + lane;
            float b1v = brow[f0 + fl];
            float b3v = brow[Fm + f0 + fl];
            float h1 = 0.f, h3 = 0.f;
            #pragma unroll
            for (int rr = 0; rr < 16; rr++) {
                h1 = fmaf(l1r[rr], B1s[rr * FCH + fl], h1);
                h3 = fmaf(l3r[rr], B3s[rr * FCH + fl], h3);
            }
            h1 = fmaf(LSCALE, h1, b1v);
            h3 = fmaf(LSCALE, h3, b3v);
            float sig = 1.f / (1.f + expf(-h1));
            float s = h1 * sig * h3;
            srow[f0 + fl] = s;
            #pragma unroll
            for (int rr = 0; rr < 16; rr++)
                l2a[rr] = fmaf(s, A2s[rr * FCH + fl], l2a[rr]);
        }
        #pragma unroll
        for (int rr = 0; rr < 16; rr++) {
            float v = l2a[rr];
            #pragma unroll
            for (int o = 16; o; o >>= 1) v += __shfl_down_sync(0xffffffffu, v, o);
            if (lane == 0)
                g_l2p[(((size_t)n * 2 + k) * NCH + ch) * 16 + rr] = v;
        }
    }
}

// ---------------- mix + bf16 split of smix (A-mode) ----------------
__global__ void mix_split_kernel() {
    int t = blockIdx.x * 256 + threadIdx.x;
    size_t idx = (size_t)t * 8;
    int n = (int)(idx / Fm);
    int f = (int)(idx - (size_t)n * Fm);
    float w0 = g_topw[2 * n], w1 = g_topw[2 * n + 1];
    const float* s0p = g_s + ((size_t)n * 2) * Fm + f;
    const float* s1p = g_s + ((size_t)n * 2 + 1) * Fm + f;
    float m[8];
    #pragma unroll
    for (int q = 0; q < 2; q++) {
        float4 a = *(const float4*)(s0p + 4 * q);
        float4 b = *(const float4*)(s1p + 4 * q);
        m[4*q+0] = w0 * a.x + w1 * b.x;
        m[4*q+1] = w0 * a.y + w1 * b.y;
        m[4*q+2] = w0 * a.z + w1 * b.z;
        m[4*q+3] = w0 * a.w + w1 * b.w;
    }
    uint32_t h[4], l[4];
    #pragma unroll
    for (int i = 0; i < 4; i++) {
        __nv_bfloat16 h0 = __float2bfloat16(m[2*i]);
        __nv_bfloat16 h1 = __float2bfloat16(m[2*i+1]);
        __nv_bfloat16 l0 = __float2bfloat16(m[2*i]   - __bfloat162float(h0));
        __nv_bfloat16 l1 = __float2bfloat16(m[2*i+1] - __bfloat162float(h1));
        __nv_bfloat162 hp; hp.x = h0; hp.y = h1;
        __nv_bfloat162 lp; lp.x = l0; lp.y = l1;
        h[i] = *(uint32_t*)&hp;
        l[i] = *(uint32_t*)&lp;
    }
    uint4 H = make_uint4(h[0], h[1], h[2], h[3]);
    uint4 L = make_uint4(l[0], l[1], l[2], l[3]);
    __nv_bfloat16* base = g_smc + (size_t)n * K3F + f;
    *(uint4*)base = H;
    *(uint4*)(base + Fm) = H;
    *(uint4*)(base + 2 * Fm) = L;
}

// ---------------- output: split-K merge + LoRA ----------------
__global__ void lora_out_kernel(const float* __restrict__ B2, float* __restrict__ out) {
    int n = blockIdx.y;
    int d = blockIdx.x * 256 + threadIdx.x;
    __shared__ float sl2[32];
    __shared__ int se[2];
    if (threadIdx.x < 32) {
        int k = threadIdx.x >> 4, rr = threadIdx.x & 15;
        float v = 0.f;
        #pragma unroll
        for (int ch = 0; ch < NCH; ch++)
            v += g_l2p[(((size_t)n * 2 + k) * NCH + ch) * 16 + rr];
        sl2[threadIdx.x] = v * g_topw[n * 2 + k] * LSCALE;
    }
    if (threadIdx.x < 2) se[threadIdx.x] = g_topi[n * 2 + threadIdx.x];
    __syncthreads();
    float acc = 0.f;
    #pragma unroll
    for (int z = 0; z < ZW2; z++)
        acc += g_wpart[(size_t)z * Ntok * Dm + (size_t)n * Dm + d];
    #pragma unroll
    for (int k = 0; k < 2; k++) {
        int e = se[k];
        const float4* bp = (const float4*)(B2 + ((size_t)e * Dm + d) * Rm);
        #pragma unroll
        for (int q = 0; q < 4; q++) {
            float4 v = bp[q];
            acc += sl2[k*16+4*q+0]*v.x + sl2[k*16+4*q+1]*v.y + sl2[k*16+4*q+2]*v.z + sl2[k*16+4*q+3]*v.w;
        }
    }
    out[(size_t)n * Dm + d] = acc;
}

// --------------------------------- launch --------------------------------
extern "C" void kernel_launch(void* const* d_in, const int* in_sizes, int n_in,
                              void* d_out, int out_size) {
    const float* x      = (const float*)d_in[0];
    const float* gate_w = (const float*)d_in[1];
    const float* W1     = (const float*)d_in[2];
    const float* W3     = (const float*)d_in[3];
    const float* W2     = (const float*)d_in[4];
    const float* A1     = (const float*)d_in[5];
    const float* B1     = (const float*)d_in[6];
    const float* A3     = (const float*)d_in[7];
    const float* B3     = (const float*)d_in[8];
    const float* A2     = (const float*)d_in[9];
    const float* B2     = (const float*)d_in[10];

    float* out    = (float*)d_out;
    float* logits = (float*)d_out + (size_t)Ntok * Dm;

    float *baseall, *wpart;
    __nv_bfloat16 *xcat, *wallc, *w2c, *smc;
    cudaGetSymbolAddress((void**)&baseall, g_baseall);
    cudaGetSymbolAddress((void**)&wpart, g_wpart);
    cudaGetSymbolAddress((void**)&xcat,  g_xcat);
    cudaGetSymbolAddress((void**)&wallc, g_wallc);
    cudaGetSymbolAddress((void**)&w2c,   g_w2c);
    cudaGetSymbolAddress((void**)&smc,   g_smc);

    cudaFuncSetAttribute(gemm_mma, cudaFuncAttributeMaxDynamicSharedMemorySize, GEMM_SMEM);
    cudaFuncSetAttribute(expert_ffn, cudaFuncAttributeMaxDynamicSharedMemorySize, EFFN_SMEM);

    // splits
    split_kernel<<<Ntok * Dm / 8 / 256, 256>>>(x, xcat, Dm, Ntok * Dm / 8, 0);
    split_kernel<<<Fm * Dm / 8 / 256, 256>>>(W1, wallc, Dm, Fm * Dm / 8, 1);
    split_kernel<<<Fm * Dm / 8 / 256, 256>>>(W3, wallc + (size_t)Fm * K3D, Dm, Fm * Dm / 8, 1);
    split_a13_kernel<<<256 * Dm / 8 / 256, 256>>>(A1, A3, wallc + (size_t)2 * Fm * K3D);
    split_kernel<<<Dm * Fm / 8 / 256, 256>>>(W2, w2c, Fm, Dm * Fm / 8, 1);

    // router + expert lists
    gate_kernel<<<Ntok, 256>>>(x, gate_w, logits);
    build_list_kernel<<<Em, 256>>>();

    // fused base GEMM: [x@W1 | x@W3 | x@A13] — persistent, 720 tiles over 592 CTAs
    {
        int ntiles = (Ntok / 128) * (NBALL / 128);      // 8 * 90 = 720
        gemm_mma<<<NPERSIST, 256, GEMM_SMEM>>>(xcat, wallc, baseall,
                                               NBALL, K3D, K3D,
                                               Ntok / 128, NBALL / 128, ntiles);
    }
    // expert-major SwiGLU + l2 partials
    {
        dim3 grid(Em, NCH);
        expert_ffn<<<grid, 256, EFFN_SMEM>>>(B1, B3, A2);
    }
    // mix + split
    mix_split_kernel<<<Ntok * Fm / 8 / 256, 256>>>();
    // down-projection GEMM, split-K=4: 8*16*4 = 512 tiles, one wave
    {
        int ntiles = (Ntok / 128) * (Dm / 128) * ZW2;   // 512
        gemm_mma<<<ntiles, 256, GEMM_SMEM>>>(smc, w2c, wpart,
                                             Dm, K3F, KPER_W2,
                                             Ntok / 128, Dm / 128, ntiles);
    }
    // merge partials + output LoRA
    {
        dim3 grid(Dm / 256, Ntok);
        lora_out_kernel<<<grid, 256>>>(B2, out);
    }
}